// round 11
// baseline (speedup 1.0000x reference)
#include <cuda_runtime.h>
#include <cuda_bf16.h>
#include <limits.h>

// Sorted-segment-sum of gathered values, output-ownership formulation:
//   out[s] = sum over j with seg[j]==s of cv[idx[j]]
// seg[] sorted ascending; empty segments 0.
//
// Warp w owns segments [32w, 32w+32). Edge range [lo, hi) found by an
// interpolation-seeded binary search over seg[] (boundaries shared per CTA).
// Strips of 256 edges (8/thread via 2x int4): per-thread run detection,
// ballot-based clamped warp scan, lane-31 carry across strips. Every owned
// segment completes exactly once -> plain SMEM store (no atomics). Final
// coalesced STG of the 32 owned outputs (zeros included -> no zero kernel).
// Pre/post edges inside aligned strips keep real seg ids; range guard on
// flush excludes them (the neighboring warps own those segments).

#define FULL 0xffffffffu
#define SPW 32              // segments per warp
#define WPB 4               // warps per block
#define NTHREADS (WPB * 32)
#define STRIP 256           // edges per warp-iteration (8 per lane)

// plain-store flush: only segments owned by this warp
#define FLUSH(sid, val)                                              \
    do {                                                             \
        int _d = (sid) - s0;                                         \
        if ((unsigned)_d < (unsigned)nseg) sums[warp][_d] = (val);   \
    } while (0)

__global__ __launch_bounds__(NTHREADS, 16)
void seg_own_kernel(const float* __restrict__ cv,
                    const int*   __restrict__ idx,
                    const int*   __restrict__ seg,
                    float*       __restrict__ out,
                    int E, int N)
{
    __shared__ int   bnd[WPB + 1];
    __shared__ float sums[WPB][SPW];

    const int lane = threadIdx.x & 31;
    const int warp = threadIdx.x >> 5;
    const int cta_s0 = blockIdx.x * (WPB * SPW);

    // warp 0, lanes 0..WPB: find edge boundaries lower_bound(seg, target)
    if (warp == 0 && lane <= WPB) {
        int target = cta_s0 + lane * SPW;
        if (target > N) target = N;
        int loB = 0, hiB = E;
        if (E > 0) {
            long long est = (long long)target * (long long)E /
                            (long long)(N > 0 ? N : 1);
            // two tightening probes; each is a valid binary-search step,
            // so correctness holds even if the statistical window misses
            long long pl = est - 16384;
            if (pl < 0) pl = 0; if (pl > E - 1) pl = E - 1;
            long long ph = est + 16384;
            if (ph < 0) ph = 0; if (ph > E - 1) ph = E - 1;
            int p = (int)pl;
            if (__ldg(&seg[p]) < target) loB = p + 1; else hiB = p;
            p = (int)ph;
            if (p >= loB && p < hiB) {
                if (__ldg(&seg[p]) < target) loB = p + 1; else hiB = p;
            }
        }
        while (loB < hiB) {
            int mid = (int)(((long long)loB + (long long)hiB) >> 1);
            if (__ldg(&seg[mid]) < target) loB = mid + 1; else hiB = mid;
        }
        bnd[lane] = loB;
    }
    sums[warp][lane] = 0.0f;
    __syncthreads();

    const int s0 = cta_s0 + warp * SPW;
    if (s0 >= N) return;
    const int nseg = (N - s0 < SPW) ? (N - s0) : SPW;
    const int lo = bnd[warp];
    const int hi = bnd[warp + 1];

    float carry     = 0.0f;
    int   carry_seg = INT_MIN;   // never matches a real segment

    const int lo4 = lo & ~3;     // int4-aligned strip start

    for (int base = lo4; base < hi; base += STRIP) {
        const int e0 = base + lane * 8;

        int4 ia = make_int4(0, 0, 0, 0), ib = make_int4(0, 0, 0, 0);
        int4 sa = make_int4(INT_MAX, INT_MAX, INT_MAX, INT_MAX), sb = sa;

        const bool ld0 = (e0 < hi);
        const bool ld1 = (e0 + 4 < hi);
        if (ld0) {
            if (e0 + 4 <= E) {
                ia = __ldcs((const int4*)(idx + e0));
                sa = __ldcs((const int4*)(seg + e0));
            } else {                       // only if E % 4 != 0 (tail)
                int m = E - e0;
                if (m > 0) { ia.x = idx[e0];     sa.x = seg[e0]; }
                if (m > 1) { ia.y = idx[e0 + 1]; sa.y = seg[e0 + 1]; }
                if (m > 2) { ia.z = idx[e0 + 2]; sa.z = seg[e0 + 2]; }
            }
        }
        if (ld1) {
            if (e0 + 8 <= E) {
                ib = __ldcs((const int4*)(idx + e0 + 4));
                sb = __ldcs((const int4*)(seg + e0 + 4));
            } else {
                int m = E - (e0 + 4);
                if (m > 0) { ib.x = idx[e0 + 4]; sb.x = seg[e0 + 4]; }
                if (m > 1) { ib.y = idx[e0 + 5]; sb.y = seg[e0 + 5]; }
                if (m > 2) { ib.z = idx[e0 + 6]; sb.z = seg[e0 + 6]; }
            }
        }

        int   s_arr[8] = { sa.x, sa.y, sa.z, sa.w, sb.x, sb.y, sb.z, sb.w };
        int   i_arr[8] = { ia.x, ia.y, ia.z, ia.w, ib.x, ib.y, ib.z, ib.w };
        float v_arr[8];

        // gather only for edges that were actually loaded (sentinel: INT_MAX)
        #pragma unroll
        for (int i = 0; i < 8; i++) {
            bool have = (s_arr[i] != INT_MAX);
            v_arr[i] = have ? __ldg(&cv[i_arr[i]]) : 0.0f;
        }

        // per-thread run detection over 8 consecutive edges
        float run = v_arr[0];
        int   rs  = s_arr[0];
        const int sfirst = s_arr[0];
        float lead = 0.0f;
        bool  leadDone = false;
        #pragma unroll
        for (int i = 1; i < 8; i++) {
            if (s_arr[i] == rs) {
                run += v_arr[i];
            } else {
                if (!leadDone) { lead = run; leadDone = true; }
                else           { FLUSH(rs, run); }   // interior: complete
                run = v_arr[i];
                rs  = s_arr[i];
            }
        }
        const float trail   = run;
        const int   slast   = rs;
        const bool  allsame = !leadDone;

        // connectivity with preceding lane / strip carry
        int  prev_slast = __shfl_up_sync(FULL, slast, 1);
        bool connected  = (lane == 0) ? (carry_seg == sfirst)
                                      : (prev_slast == sfirst);

        float sv = trail;
        if (lane == 0 && connected && allsame) sv += carry;
        bool f = (lane == 0) || !allsame || !connected;

        unsigned head_mask = __ballot_sync(FULL, f);     // bit0 always set
        unsigned mask_le   = head_mask & (FULL >> (31 - lane));
        int seg_start = 31 - __clz(mask_le);
        #pragma unroll
        for (int d = 1; d < 32; d <<= 1) {
            float y = __shfl_up_sync(FULL, sv, d);
            if (lane - d >= seg_start) sv += y;
        }

        float inc_prev = __shfl_up_sync(FULL, sv, 1);
        if (lane == 0) inc_prev = carry;

        if (!allsame) {                      // leading run completes here
            float add = lead + (connected ? inc_prev : 0.0f);
            FLUSH(sfirst, add);
        }
        if (lane == 0 && !connected) {       // previous strip's carry completes
            FLUSH(carry_seg, carry);
        }

        int  next_sfirst    = __shfl_down_sync(FULL, sfirst, 1);
        bool next_connected = (lane < 31) && (next_sfirst == slast);
        if (lane < 31 && !next_connected) {
            FLUSH(slast, sv);
        }

        carry     = __shfl_sync(FULL, sv, 31);
        carry_seg = __shfl_sync(FULL, slast, 31);
    }

    FLUSH(carry_seg, carry);                 // final pending segment

    __syncwarp();
    if (lane < nseg) out[s0 + lane] = sums[warp][lane];
}

extern "C" void kernel_launch(void* const* d_in, const int* in_sizes, int n_in,
                              void* d_out, int out_size)
{
    const float* cv  = (const float*)d_in[0];
    const int*   idx = (const int*)d_in[1];
    const int*   seg = (const int*)d_in[2];
    float*       out = (float*)d_out;

    const int E = in_sizes[1];
    const int N = out_size;

    static bool carveout_set = false;
    if (!carveout_set) {
        cudaFuncSetAttribute(seg_own_kernel,
                             cudaFuncAttributePreferredSharedMemoryCarveout, 0);
        carveout_set = true;
    }

    const int segs_per_cta = WPB * SPW;                   // 128
    const int n_blocks = (N + segs_per_cta - 1) / segs_per_cta;
    seg_own_kernel<<<n_blocks, NTHREADS>>>(cv, idx, seg, out, E, N);
}

// round 13
// speedup vs baseline: 1.2325x; 1.2325x over previous
#include <cuda_runtime.h>
#include <cuda_bf16.h>
#include <limits.h>

// Sorted-segment-sum of gathered values, output-ownership, two-phase:
//   out[s] = sum over j with seg[j]==s of cv[idx[j]]
//
// Phase A: one thread per warp-boundary computes lower_bound(seg, w*SPW)
//          (interpolation-seeded) into __device__ g_bnd. Fully parallel.
// Phase B: warp w owns segments [w*SPW, w*SPW+SPW); reads [lo,hi) from
//          g_bnd; processes 256-edge strips (8/thread, 2x int4 loads,
//          run detection + ballot-scan + lane-31 carry); every owned
//          segment completes exactly once -> plain SMEM store (no atomics);
//          final coalesced STG (zeros included -> no zero-init kernel).

#define FULL 0xffffffffu
#define SPW 64              // segments per warp
#define WPB 8               // warps per block (256 threads)
#define NTHREADS (WPB * 32)
#define STRIP 256           // edges per warp-iteration (8 per lane)
#define MAX_BND (1 << 20)   // boundaries (supports N up to ~64M)

__device__ int g_bnd[MAX_BND];

// plain-store flush: only segments owned by this warp land
#define FLUSH(sid, val)                                                   \
    do {                                                                  \
        int _d = (sid) - s0;                                              \
        if ((unsigned)_d < (unsigned)nseg) sums[warp][_d] = (val);        \
    } while (0)

__global__ void bounds_kernel(const int* __restrict__ seg, int E, int N, int NB)
{
    int b = blockIdx.x * blockDim.x + threadIdx.x;
    if (b > NB) return;

    long long t64 = (long long)b * SPW;
    int target = (t64 > (long long)N) ? N : (int)t64;

    int loB = 0, hiB = E;
    if (E > 0 && N > 0) {
        long long est = (long long)target * (long long)E / (long long)N;
        const long long W = 32768;
        long long l = est - W; if (l < 0) l = 0;
        long long h = est + W; if (h > (long long)E) h = (long long)E;
        bool ok_lo = (l == 0) || (__ldg(&seg[(int)l - 1]) < target);
        bool ok_hi = (h == (long long)E) || (__ldg(&seg[(int)h]) >= target);
        if (ok_lo && ok_hi) { loB = (int)l; hiB = (int)h; }
    }
    while (loB < hiB) {
        int mid = (int)(((unsigned)loB + (unsigned)hiB) >> 1);
        if (__ldg(&seg[mid]) < target) loB = mid + 1; else hiB = mid;
    }
    g_bnd[b] = loB;
}

__global__ __launch_bounds__(NTHREADS, 8)
void seg_own_kernel(const float* __restrict__ cv,
                    const int*   __restrict__ idx,
                    const int*   __restrict__ seg,
                    float*       __restrict__ out,
                    int E, int N)
{
    __shared__ float sums[WPB][SPW];

    const int lane = threadIdx.x & 31;
    const int warp = threadIdx.x >> 5;
    const int gw   = blockIdx.x * WPB + warp;   // global warp id

    const long long s0_64 = (long long)gw * SPW;
    if (s0_64 >= (long long)N) return;
    const int s0   = (int)s0_64;
    const int nseg = (N - s0 < SPW) ? (N - s0) : SPW;

    #pragma unroll
    for (int i = lane; i < SPW; i += 32) sums[warp][i] = 0.0f;
    __syncwarp();

    const int lo = __ldg(&g_bnd[gw]);
    const int hi = __ldg(&g_bnd[gw + 1]);

    float carry     = 0.0f;
    int   carry_seg = INT_MIN;   // never matches a real segment

    const int lo4 = lo & ~3;     // int4-aligned strip start

    for (int base = lo4; base < hi; base += STRIP) {
        const int e0 = base + lane * 8;

        int4 ia = make_int4(0, 0, 0, 0), ib = make_int4(0, 0, 0, 0);
        int4 sa = make_int4(INT_MAX, INT_MAX, INT_MAX, INT_MAX), sb = sa;

        const bool ld0 = (e0 < hi);
        const bool ld1 = (e0 + 4 < hi);
        if (ld0) {
            if (e0 + 4 <= E) {
                ia = __ldcs((const int4*)(idx + e0));
                sa = __ldcs((const int4*)(seg + e0));
            } else {                      // only if E % 4 != 0
                int m = E - e0;
                if (m > 0) { ia.x = idx[e0];     sa.x = seg[e0]; }
                if (m > 1) { ia.y = idx[e0 + 1]; sa.y = seg[e0 + 1]; }
                if (m > 2) { ia.z = idx[e0 + 2]; sa.z = seg[e0 + 2]; }
            }
        }
        if (ld1) {
            if (e0 + 8 <= E) {
                ib = __ldcs((const int4*)(idx + e0 + 4));
                sb = __ldcs((const int4*)(seg + e0 + 4));
            } else {
                int m = E - (e0 + 4);
                if (m > 0) { ib.x = idx[e0 + 4]; sb.x = seg[e0 + 4]; }
                if (m > 1) { ib.y = idx[e0 + 5]; sb.y = seg[e0 + 5]; }
                if (m > 2) { ib.z = idx[e0 + 6]; sb.z = seg[e0 + 6]; }
            }
        }

        int   s_arr[8] = { sa.x, sa.y, sa.z, sa.w, sb.x, sb.y, sb.z, sb.w };
        int   i_arr[8] = { ia.x, ia.y, ia.z, ia.w, ib.x, ib.y, ib.z, ib.w };
        float v_arr[8];

        #pragma unroll
        for (int i = 0; i < 8; i++) {
            bool have = (s_arr[i] != INT_MAX);
            v_arr[i] = have ? __ldg(&cv[i_arr[i]]) : 0.0f;
        }

        // per-thread run detection over 8 consecutive edges
        float run = v_arr[0];
        int   rs  = s_arr[0];
        const int sfirst = s_arr[0];
        float lead = 0.0f;
        bool  leadDone = false;
        #pragma unroll
        for (int i = 1; i < 8; i++) {
            if (s_arr[i] == rs) {
                run += v_arr[i];
            } else {
                if (!leadDone) { lead = run; leadDone = true; }
                else           { FLUSH(rs, run); }   // interior: complete
                run = v_arr[i];
                rs  = s_arr[i];
            }
        }
        const float trail   = run;
        const int   slast   = rs;
        const bool  allsame = !leadDone;

        // connectivity with preceding lane / strip carry
        int  prev_slast = __shfl_up_sync(FULL, slast, 1);
        bool connected  = (lane == 0) ? (carry_seg == sfirst)
                                      : (prev_slast == sfirst);

        float sv = trail;
        if (lane == 0 && connected && allsame) sv += carry;
        bool f = (lane == 0) || !allsame || !connected;

        unsigned head_mask = __ballot_sync(FULL, f);     // bit0 always set
        unsigned mask_le   = head_mask & (FULL >> (31 - lane));
        int seg_start = 31 - __clz(mask_le);
        #pragma unroll
        for (int d = 1; d < 32; d <<= 1) {
            float y = __shfl_up_sync(FULL, sv, d);
            if (lane - d >= seg_start) sv += y;
        }

        float inc_prev = __shfl_up_sync(FULL, sv, 1);
        if (lane == 0) inc_prev = carry;

        if (!allsame) {                      // leading run completes here
            float add = lead + (connected ? inc_prev : 0.0f);
            FLUSH(sfirst, add);
        }
        if (lane == 0 && !connected) {       // previous strip's carry completes
            FLUSH(carry_seg, carry);
        }

        int  next_sfirst    = __shfl_down_sync(FULL, sfirst, 1);
        bool next_connected = (lane < 31) && (next_sfirst == slast);
        if (lane < 31 && !next_connected) {
            FLUSH(slast, sv);
        }

        carry     = __shfl_sync(FULL, sv, 31);
        carry_seg = __shfl_sync(FULL, slast, 31);
    }

    FLUSH(carry_seg, carry);                 // final pending segment

    __syncwarp();
    #pragma unroll
    for (int i = lane; i < SPW; i += 32) {
        if (i < nseg) out[s0 + i] = sums[warp][i];
    }
}

extern "C" void kernel_launch(void* const* d_in, const int* in_sizes, int n_in,
                              void* d_out, int out_size)
{
    const float* cv  = (const float*)d_in[0];
    const int*   idx = (const int*)d_in[1];
    const int*   seg = (const int*)d_in[2];
    float*       out = (float*)d_out;

    const int E = in_sizes[1];
    const int N = out_size;

    static bool carveout_set = false;
    if (!carveout_set) {
        cudaFuncSetAttribute(seg_own_kernel,
                             cudaFuncAttributePreferredSharedMemoryCarveout, 0);
        carveout_set = true;
    }

    const int NB = (N + SPW - 1) / SPW;      // number of owning warps

    // Phase A: boundary searches (NB+1 threads)
    {
        int threads = 256;
        int blocks  = (NB + 1 + threads - 1) / threads;
        bounds_kernel<<<blocks, threads>>>(seg, E, N, NB);
    }

    // Phase B: ownership segmented sum
    {
        int blocks = (NB + WPB - 1) / WPB;
        seg_own_kernel<<<blocks, NTHREADS>>>(cv, idx, seg, out, E, N);
    }
}

// round 14
// speedup vs baseline: 1.2370x; 1.0036x over previous
#include <cuda_runtime.h>
#include <cuda_bf16.h>
#include <limits.h>

// Sorted-segment-sum of gathered values, output-ownership, two-phase:
//   out[s] = sum over j with seg[j]==s of cv[idx[j]]
//
// Phase A: one thread per warp-boundary computes lower_bound(seg, w*SPW)
//          (interpolation-seeded) into __device__ g_bnd. Fully parallel.
// Phase B: warp w owns segments [w*SPW, w*SPW+SPW); reads [lo,hi) from
//          g_bnd; processes 256-edge strips (8/thread, 2x int4 loads,
//          run detection + ballot-scan + lane-31 carry); every owned
//          segment completes exactly once -> plain SMEM store (no atomics);
//          final coalesced STG (zeros included -> no zero-init kernel).

#define FULL 0xffffffffu
#define SPW 64              // segments per warp
#define WPB 8               // warps per block (256 threads)
#define NTHREADS (WPB * 32)
#define STRIP 256           // edges per warp-iteration (8 per lane)
#define MAX_BND (1 << 20)   // boundaries (supports N up to ~64M)

__device__ int g_bnd[MAX_BND];

// plain-store flush: only segments owned by this warp land
#define FLUSH(sid, val)                                                   \
    do {                                                                  \
        int _d = (sid) - s0;                                              \
        if ((unsigned)_d < (unsigned)nseg) sums[warp][_d] = (val);        \
    } while (0)

__global__ void bounds_kernel(const int* __restrict__ seg, int E, int N, int NB)
{
    int b = blockIdx.x * blockDim.x + threadIdx.x;
    if (b > NB) return;

    long long t64 = (long long)b * SPW;
    int target = (t64 > (long long)N) ? N : (int)t64;

    int loB = 0, hiB = E;
    if (E > 0 && N > 0) {
        long long est = (long long)target * (long long)E / (long long)N;
        const long long W = 32768;
        long long l = est - W; if (l < 0) l = 0;
        long long h = est + W; if (h > (long long)E) h = (long long)E;
        bool ok_lo = (l == 0) || (__ldg(&seg[(int)l - 1]) < target);
        bool ok_hi = (h == (long long)E) || (__ldg(&seg[(int)h]) >= target);
        if (ok_lo && ok_hi) { loB = (int)l; hiB = (int)h; }
    }
    while (loB < hiB) {
        int mid = (int)(((unsigned)loB + (unsigned)hiB) >> 1);
        if (__ldg(&seg[mid]) < target) loB = mid + 1; else hiB = mid;
    }
    g_bnd[b] = loB;
}

__global__ __launch_bounds__(NTHREADS, 8)
void seg_own_kernel(const float* __restrict__ cv,
                    const int*   __restrict__ idx,
                    const int*   __restrict__ seg,
                    float*       __restrict__ out,
                    int E, int N)
{
    __shared__ float sums[WPB][SPW];

    const int lane = threadIdx.x & 31;
    const int warp = threadIdx.x >> 5;
    const int gw   = blockIdx.x * WPB + warp;   // global warp id

    const long long s0_64 = (long long)gw * SPW;
    if (s0_64 >= (long long)N) return;
    const int s0   = (int)s0_64;
    const int nseg = (N - s0 < SPW) ? (N - s0) : SPW;

    #pragma unroll
    for (int i = lane; i < SPW; i += 32) sums[warp][i] = 0.0f;
    __syncwarp();

    const int lo = __ldg(&g_bnd[gw]);
    const int hi = __ldg(&g_bnd[gw + 1]);

    float carry     = 0.0f;
    int   carry_seg = INT_MIN;   // never matches a real segment

    const int lo4 = lo & ~3;     // int4-aligned strip start

    for (int base = lo4; base < hi; base += STRIP) {
        const int e0 = base + lane * 8;

        int4 ia = make_int4(0, 0, 0, 0), ib = make_int4(0, 0, 0, 0);
        int4 sa = make_int4(INT_MAX, INT_MAX, INT_MAX, INT_MAX), sb = sa;

        const bool ld0 = (e0 < hi);
        const bool ld1 = (e0 + 4 < hi);
        if (ld0) {
            if (e0 + 4 <= E) {
                ia = __ldcs((const int4*)(idx + e0));
                sa = __ldcs((const int4*)(seg + e0));
            } else {                      // only if E % 4 != 0
                int m = E - e0;
                if (m > 0) { ia.x = idx[e0];     sa.x = seg[e0]; }
                if (m > 1) { ia.y = idx[e0 + 1]; sa.y = seg[e0 + 1]; }
                if (m > 2) { ia.z = idx[e0 + 2]; sa.z = seg[e0 + 2]; }
            }
        }
        if (ld1) {
            if (e0 + 8 <= E) {
                ib = __ldcs((const int4*)(idx + e0 + 4));
                sb = __ldcs((const int4*)(seg + e0 + 4));
            } else {
                int m = E - (e0 + 4);
                if (m > 0) { ib.x = idx[e0 + 4]; sb.x = seg[e0 + 4]; }
                if (m > 1) { ib.y = idx[e0 + 5]; sb.y = seg[e0 + 5]; }
                if (m > 2) { ib.z = idx[e0 + 6]; sb.z = seg[e0 + 6]; }
            }
        }

        int   s_arr[8] = { sa.x, sa.y, sa.z, sa.w, sb.x, sb.y, sb.z, sb.w };
        int   i_arr[8] = { ia.x, ia.y, ia.z, ia.w, ib.x, ib.y, ib.z, ib.w };
        float v_arr[8];

        #pragma unroll
        for (int i = 0; i < 8; i++) {
            bool have = (s_arr[i] != INT_MAX);
            v_arr[i] = have ? __ldg(&cv[i_arr[i]]) : 0.0f;
        }

        // per-thread run detection over 8 consecutive edges
        float run = v_arr[0];
        int   rs  = s_arr[0];
        const int sfirst = s_arr[0];
        float lead = 0.0f;
        bool  leadDone = false;
        #pragma unroll
        for (int i = 1; i < 8; i++) {
            if (s_arr[i] == rs) {
                run += v_arr[i];
            } else {
                if (!leadDone) { lead = run; leadDone = true; }
                else           { FLUSH(rs, run); }   // interior: complete
                run = v_arr[i];
                rs  = s_arr[i];
            }
        }
        const float trail   = run;
        const int   slast   = rs;
        const bool  allsame = !leadDone;

        // connectivity with preceding lane / strip carry
        int  prev_slast = __shfl_up_sync(FULL, slast, 1);
        bool connected  = (lane == 0) ? (carry_seg == sfirst)
                                      : (prev_slast == sfirst);

        float sv = trail;
        if (lane == 0 && connected && allsame) sv += carry;
        bool f = (lane == 0) || !allsame || !connected;

        unsigned head_mask = __ballot_sync(FULL, f);     // bit0 always set
        unsigned mask_le   = head_mask & (FULL >> (31 - lane));
        int seg_start = 31 - __clz(mask_le);
        #pragma unroll
        for (int d = 1; d < 32; d <<= 1) {
            float y = __shfl_up_sync(FULL, sv, d);
            if (lane - d >= seg_start) sv += y;
        }

        float inc_prev = __shfl_up_sync(FULL, sv, 1);
        if (lane == 0) inc_prev = carry;

        if (!allsame) {                      // leading run completes here
            float add = lead + (connected ? inc_prev : 0.0f);
            FLUSH(sfirst, add);
        }
        if (lane == 0 && !connected) {       // previous strip's carry completes
            FLUSH(carry_seg, carry);
        }

        int  next_sfirst    = __shfl_down_sync(FULL, sfirst, 1);
        bool next_connected = (lane < 31) && (next_sfirst == slast);
        if (lane < 31 && !next_connected) {
            FLUSH(slast, sv);
        }

        carry     = __shfl_sync(FULL, sv, 31);
        carry_seg = __shfl_sync(FULL, slast, 31);
    }

    FLUSH(carry_seg, carry);                 // final pending segment

    __syncwarp();
    #pragma unroll
    for (int i = lane; i < SPW; i += 32) {
        if (i < nseg) out[s0 + i] = sums[warp][i];
    }
}

extern "C" void kernel_launch(void* const* d_in, const int* in_sizes, int n_in,
                              void* d_out, int out_size)
{
    const float* cv  = (const float*)d_in[0];
    const int*   idx = (const int*)d_in[1];
    const int*   seg = (const int*)d_in[2];
    float*       out = (float*)d_out;

    const int E = in_sizes[1];
    const int N = out_size;

    static bool carveout_set = false;
    if (!carveout_set) {
        cudaFuncSetAttribute(seg_own_kernel,
                             cudaFuncAttributePreferredSharedMemoryCarveout, 0);
        carveout_set = true;
    }

    const int NB = (N + SPW - 1) / SPW;      // number of owning warps

    // Phase A: boundary searches (NB+1 threads)
    {
        int threads = 256;
        int blocks  = (NB + 1 + threads - 1) / threads;
        bounds_kernel<<<blocks, threads>>>(seg, E, N, NB);
    }

    // Phase B: ownership segmented sum
    {
        int blocks = (NB + WPB - 1) / WPB;
        seg_own_kernel<<<blocks, NTHREADS>>>(cv, idx, seg, out, E, N);
    }
}

// round 15
// speedup vs baseline: 1.3380x; 1.0816x over previous
#include <cuda_runtime.h>
#include <cuda_bf16.h>
#include <limits.h>

// Sorted-segment-sum of gathered values, output-ownership, two-phase:
//   out[s] = sum over j with seg[j]==s of cv[idx[j]]
//
// Phase A: one thread per warp-boundary computes lower_bound(seg, w*SPW)
//          (interpolation-seeded) into __device__ g_bnd. Fully parallel.
// Phase B: warp w owns segments [w*SPW, w*SPW+SPW) (SPW=16 -> 62.5K warps,
//          grid 7813 CTAs: the occupancy/backfill regime proven in R2-R5).
//          256-edge strips (8/thread, 2x int4 loads, run detection +
//          ballot-scan + lane-31 carry); every owned segment completes
//          exactly once -> plain SMEM store (no atomics); final coalesced
//          STG (zeros included -> no zero-init kernel).

#define FULL 0xffffffffu
#define SPW 16              // segments per warp (~512 edges avg)
#define WPB 8               // warps per block (256 threads)
#define NTHREADS (WPB * 32)
#define STRIP 256           // edges per warp-iteration (8 per lane)
#define MAX_BND (1 << 22)   // boundaries (supports N up to ~64M)

__device__ int g_bnd[MAX_BND];

// plain-store flush: only segments owned by this warp land
#define FLUSH(sid, val)                                                   \
    do {                                                                  \
        int _d = (sid) - s0;                                              \
        if ((unsigned)_d < (unsigned)nseg) sums[warp][_d] = (val);        \
    } while (0)

__global__ void bounds_kernel(const int* __restrict__ seg, int E, int N, int NB)
{
    int b = blockIdx.x * blockDim.x + threadIdx.x;
    if (b > NB) return;

    long long t64 = (long long)b * SPW;
    int target = (t64 > (long long)N) ? N : (int)t64;

    int loB = 0, hiB = E;
    if (E > 0 && N > 0) {
        long long est = (long long)target * (long long)E / (long long)N;
        const long long W = 16384;
        long long l = est - W; if (l < 0) l = 0;
        long long h = est + W; if (h > (long long)E) h = (long long)E;
        bool ok_lo = (l == 0) || (__ldg(&seg[(int)l - 1]) < target);
        bool ok_hi = (h == (long long)E) || (__ldg(&seg[(int)h]) >= target);
        if (ok_lo && ok_hi) { loB = (int)l; hiB = (int)h; }
    }
    while (loB < hiB) {
        int mid = (int)(((unsigned)loB + (unsigned)hiB) >> 1);
        if (__ldg(&seg[mid]) < target) loB = mid + 1; else hiB = mid;
    }
    g_bnd[b] = loB;
}

__global__ __launch_bounds__(NTHREADS, 8)
void seg_own_kernel(const float* __restrict__ cv,
                    const int*   __restrict__ idx,
                    const int*   __restrict__ seg,
                    float*       __restrict__ out,
                    int E, int N)
{
    __shared__ float sums[WPB][SPW];

    const int lane = threadIdx.x & 31;
    const int warp = threadIdx.x >> 5;
    const int gw   = blockIdx.x * WPB + warp;   // global warp id

    const long long s0_64 = (long long)gw * SPW;
    if (s0_64 >= (long long)N) return;
    const int s0   = (int)s0_64;
    const int nseg = (N - s0 < SPW) ? (N - s0) : SPW;

    if (lane < SPW) sums[warp][lane] = 0.0f;
    __syncwarp();

    const int lo = __ldg(&g_bnd[gw]);
    const int hi = __ldg(&g_bnd[gw + 1]);

    float carry     = 0.0f;
    int   carry_seg = INT_MIN;   // never matches a real segment

    const int lo4 = lo & ~3;     // int4-aligned strip start

    for (int base = lo4; base < hi; base += STRIP) {
        const int e0 = base + lane * 8;

        int4 ia = make_int4(0, 0, 0, 0), ib = make_int4(0, 0, 0, 0);
        int4 sa = make_int4(INT_MAX, INT_MAX, INT_MAX, INT_MAX), sb = sa;

        const bool ld0 = (e0 < hi);
        const bool ld1 = (e0 + 4 < hi);
        if (ld0) {
            if (e0 + 4 <= E) {
                ia = __ldcs((const int4*)(idx + e0));
                sa = __ldcs((const int4*)(seg + e0));
            } else {                      // only if E % 4 != 0
                int m = E - e0;
                if (m > 0) { ia.x = idx[e0];     sa.x = seg[e0]; }
                if (m > 1) { ia.y = idx[e0 + 1]; sa.y = seg[e0 + 1]; }
                if (m > 2) { ia.z = idx[e0 + 2]; sa.z = seg[e0 + 2]; }
            }
        }
        if (ld1) {
            if (e0 + 8 <= E) {
                ib = __ldcs((const int4*)(idx + e0 + 4));
                sb = __ldcs((const int4*)(seg + e0 + 4));
            } else {
                int m = E - (e0 + 4);
                if (m > 0) { ib.x = idx[e0 + 4]; sb.x = seg[e0 + 4]; }
                if (m > 1) { ib.y = idx[e0 + 5]; sb.y = seg[e0 + 5]; }
                if (m > 2) { ib.z = idx[e0 + 6]; sb.z = seg[e0 + 6]; }
            }
        }

        int   s_arr[8] = { sa.x, sa.y, sa.z, sa.w, sb.x, sb.y, sb.z, sb.w };
        int   i_arr[8] = { ia.x, ia.y, ia.z, ia.w, ib.x, ib.y, ib.z, ib.w };
        float v_arr[8];

        #pragma unroll
        for (int i = 0; i < 8; i++) {
            bool have = (s_arr[i] != INT_MAX);
            v_arr[i] = have ? __ldg(&cv[i_arr[i]]) : 0.0f;
        }

        // per-thread run detection over 8 consecutive edges
        float run = v_arr[0];
        int   rs  = s_arr[0];
        const int sfirst = s_arr[0];
        float lead = 0.0f;
        bool  leadDone = false;
        #pragma unroll
        for (int i = 1; i < 8; i++) {
            if (s_arr[i] == rs) {
                run += v_arr[i];
            } else {
                if (!leadDone) { lead = run; leadDone = true; }
                else           { FLUSH(rs, run); }   // interior: complete
                run = v_arr[i];
                rs  = s_arr[i];
            }
        }
        const float trail   = run;
        const int   slast   = rs;
        const bool  allsame = !leadDone;

        // connectivity with preceding lane / strip carry
        int  prev_slast = __shfl_up_sync(FULL, slast, 1);
        bool connected  = (lane == 0) ? (carry_seg == sfirst)
                                      : (prev_slast == sfirst);

        float sv = trail;
        if (lane == 0 && connected && allsame) sv += carry;
        bool f = (lane == 0) || !allsame || !connected;

        unsigned head_mask = __ballot_sync(FULL, f);     // bit0 always set
        unsigned mask_le   = head_mask & (FULL >> (31 - lane));
        int seg_start = 31 - __clz(mask_le);
        #pragma unroll
        for (int d = 1; d < 32; d <<= 1) {
            float y = __shfl_up_sync(FULL, sv, d);
            if (lane - d >= seg_start) sv += y;
        }

        float inc_prev = __shfl_up_sync(FULL, sv, 1);
        if (lane == 0) inc_prev = carry;

        if (!allsame) {                      // leading run completes here
            float add = lead + (connected ? inc_prev : 0.0f);
            FLUSH(sfirst, add);
        }
        if (lane == 0 && !connected) {       // previous strip's carry completes
            FLUSH(carry_seg, carry);
        }

        int  next_sfirst    = __shfl_down_sync(FULL, sfirst, 1);
        bool next_connected = (lane < 31) && (next_sfirst == slast);
        if (lane < 31 && !next_connected) {
            FLUSH(slast, sv);
        }

        carry     = __shfl_sync(FULL, sv, 31);
        carry_seg = __shfl_sync(FULL, slast, 31);
    }

    FLUSH(carry_seg, carry);                 // final pending segment

    __syncwarp();
    if (lane < nseg) out[s0 + lane] = sums[warp][lane];
}

extern "C" void kernel_launch(void* const* d_in, const int* in_sizes, int n_in,
                              void* d_out, int out_size)
{
    const float* cv  = (const float*)d_in[0];
    const int*   idx = (const int*)d_in[1];
    const int*   seg = (const int*)d_in[2];
    float*       out = (float*)d_out;

    const int E = in_sizes[1];
    const int N = out_size;

    static bool carveout_set = false;
    if (!carveout_set) {
        cudaFuncSetAttribute(seg_own_kernel,
                             cudaFuncAttributePreferredSharedMemoryCarveout, 0);
        carveout_set = true;
    }

    const int NB = (N + SPW - 1) / SPW;      // number of owning warps

    // Phase A: boundary searches (NB+1 threads, fully parallel)
    {
        int threads = 256;
        int blocks  = (NB + 1 + threads - 1) / threads;
        bounds_kernel<<<blocks, threads>>>(seg, E, N, NB);
    }

    // Phase B: ownership segmented sum
    {
        int blocks = (NB + WPB - 1) / WPB;
        seg_own_kernel<<<blocks, NTHREADS>>>(cv, idx, seg, out, E, N);
    }
}